// round 1
// baseline (speedup 1.0000x reference)
#include <cuda_runtime.h>
#include <math.h>

#define BATCH 4
#define NG 1024
#define NC 1024
#define NQ 256
#define NF 512
#define NH 8
#define HD 64
#define NL 2
#define ALPHAF 0.2f
#define NEGV -9e15f

// ---------------- scratch (device globals; no allocation allowed) ----------------
__device__ float g_Ga[BATCH*NG*NF];   // gloss after layer 0
__device__ float g_Ca[BATCH*NC*NF];   // clip after layer 0
__device__ float g_Qa[BATCH*NQ*NF];   // question after layer 0
__device__ float g_G1[BATCH*NG*NF];   // gloss_1 within a layer
__device__ float g_AGG[BATCH*NG*NF];  // gloss_same / *_agg scratch
__device__ float g_Pq[BATCH*NG*NF];   // query projection
__device__ float g_Pk[BATCH*NG*NF];   // key projection
__device__ float g_T1[BATCH*NG*NF];   // fusion tmp new_a
__device__ float g_T2[BATCH*NG*NF];   // fusion tmp gate pre-sigmoid
__device__ float g_Wt[NF*NF];         // transposed attention W
__device__ float g_s1[BATCH*NH*NG];
__device__ float g_s2[BATCH*NH*NG];
__device__ float g_cmax[BATCH*NH*NG];
__device__ float g_csum[BATCH*NH*NG];

// ---------------- generic fp32 GEMM: C (+)= A[M,K] @ B[K,N] ----------------
// 64x64 tile, BK=16, 256 threads, 4x4 per thread. Requires M%64==0, N%64==0, K%16==0.
template<int ACC>
__global__ __launch_bounds__(256) void gemm_nn(const float* __restrict__ A,
                                               const float* __restrict__ B,
                                               float* __restrict__ C,
                                               int M, int N, int K) {
    __shared__ float As[16][64];
    __shared__ float Bs[16][64];
    const int tid = threadIdx.x;
    const int tx = tid & 15, ty = tid >> 4;
    const int row0 = blockIdx.y * 64, col0 = blockIdx.x * 64;
    const int ra = tid >> 2, ka = (tid & 3) << 2;       // A tile: 64 rows x 16 k
    const int kb = tid >> 4, cb = (tid & 15) << 2;      // B tile: 16 k x 64 cols
    float acc[4][4] = {};
    for (int k0 = 0; k0 < K; k0 += 16) {
        float4 av = *(const float4*)(A + (size_t)(row0 + ra) * K + k0 + ka);
        As[ka + 0][ra] = av.x; As[ka + 1][ra] = av.y;
        As[ka + 2][ra] = av.z; As[ka + 3][ra] = av.w;
        float4 bv = *(const float4*)(B + (size_t)(k0 + kb) * N + col0 + cb);
        Bs[kb][cb + 0] = bv.x; Bs[kb][cb + 1] = bv.y;
        Bs[kb][cb + 2] = bv.z; Bs[kb][cb + 3] = bv.w;
        __syncthreads();
#pragma unroll
        for (int k = 0; k < 16; k++) {
            float a_[4], b_[4];
#pragma unroll
            for (int i = 0; i < 4; i++) a_[i] = As[k][(ty << 2) + i];
#pragma unroll
            for (int j = 0; j < 4; j++) b_[j] = Bs[k][(tx << 2) + j];
#pragma unroll
            for (int i = 0; i < 4; i++)
#pragma unroll
                for (int j = 0; j < 4; j++) acc[i][j] += a_[i] * b_[j];
        }
        __syncthreads();
    }
#pragma unroll
    for (int i = 0; i < 4; i++) {
        int r = row0 + (ty << 2) + i;
#pragma unroll
        for (int j = 0; j < 4; j++) {
            int c = col0 + (tx << 2) + j;
            if (ACC) C[(size_t)r * N + c] += acc[i][j];
            else     C[(size_t)r * N + c]  = acc[i][j];
        }
    }
}

// ---------------- gloss_same: C[b,m,f] = sum_n adj[b,n,m] * X[b,n,f] ----------------
__global__ __launch_bounds__(256) void gemm_adjT(const int* __restrict__ adj,
                                                 const float* __restrict__ X,
                                                 float* __restrict__ C,
                                                 int N, int Mo, int F_) {
    const int b = blockIdx.z;
    const int* A = adj + (size_t)b * N * Mo;
    const float* Xb = X + (size_t)b * N * F_;
    float* Cb = C + (size_t)b * Mo * F_;
    __shared__ float As[16][64];   // [n][m]
    __shared__ float Bs[16][64];   // [n][f]
    const int tid = threadIdx.x;
    const int tx = tid & 15, ty = tid >> 4;
    const int m0 = blockIdx.y * 64, f0 = blockIdx.x * 64;
    const int na = tid >> 4, ca = (tid & 15) << 2;
    float acc[4][4] = {};
    for (int n0 = 0; n0 < N; n0 += 16) {
        int4 av = *(const int4*)(A + (size_t)(n0 + na) * Mo + m0 + ca);
        As[na][ca + 0] = (float)av.x; As[na][ca + 1] = (float)av.y;
        As[na][ca + 2] = (float)av.z; As[na][ca + 3] = (float)av.w;
        float4 bv = *(const float4*)(Xb + (size_t)(n0 + na) * F_ + f0 + ca);
        Bs[na][ca + 0] = bv.x; Bs[na][ca + 1] = bv.y;
        Bs[na][ca + 2] = bv.z; Bs[na][ca + 3] = bv.w;
        __syncthreads();
#pragma unroll
        for (int k = 0; k < 16; k++) {
            float a_[4], b_[4];
#pragma unroll
            for (int i = 0; i < 4; i++) a_[i] = As[k][(ty << 2) + i];
#pragma unroll
            for (int j = 0; j < 4; j++) b_[j] = Bs[k][(tx << 2) + j];
#pragma unroll
            for (int i = 0; i < 4; i++)
#pragma unroll
                for (int j = 0; j < 4; j++) acc[i][j] += a_[i] * b_[j];
        }
        __syncthreads();
    }
#pragma unroll
    for (int i = 0; i < 4; i++) {
        int m = m0 + (ty << 2) + i;
#pragma unroll
        for (int j = 0; j < 4; j++)
            Cb[(size_t)m * F_ + f0 + (tx << 2) + j] = acc[i][j];
    }
}

// ---------------- W [H,F,D] -> Wt [F, H*D] ----------------
__global__ void transposeW(const float* __restrict__ W, float* __restrict__ Wt) {
    int i = blockIdx.x * blockDim.x + threadIdx.x;   // i enumerates (f,h,d)
    if (i >= NF * NH * HD) return;
    int d = i & (HD - 1);
    int h = (i >> 6) & (NH - 1);
    int f = i >> 9;
    Wt[i] = W[((size_t)h * NF + f) * HD + d];
}

// ---------------- s[b,h,n] = dot(P[b,n,h*64:...], a[h,:]) ----------------
__global__ void scores_k(const float* __restrict__ P, const float* __restrict__ a,
                         float* __restrict__ s, int Ntok) {
    int i = blockIdx.x * blockDim.x + threadIdx.x;
    if (i >= BATCH * NH * Ntok) return;
    int n = i % Ntok;
    int h = (i / Ntok) % NH;
    int b = i / (Ntok * NH);
    const float* row = P + ((size_t)(b * Ntok + n)) * NF + h * HD;
    const float* av = a + h * HD;
    float acc = 0.f;
#pragma unroll
    for (int d = 0; d < HD; d++) acc += row[d] * av[d];
    s[i] = acc;   // i == (b*NH + h)*Ntok + n
}

// ---------------- per-column (over n) online max/sum of masked lrelu scores ----------------
__global__ __launch_bounds__(256) void colstats_k(const int* __restrict__ adj, int adjT,
                                                  const float* __restrict__ s1,
                                                  const float* __restrict__ s2,
                                                  float* __restrict__ cmax,
                                                  float* __restrict__ csum,
                                                  int N, int M) {
    const int m = blockIdx.x, b = blockIdx.y;
    float mx[NH], sm[NH], s2v[NH];
#pragma unroll
    for (int h = 0; h < NH; h++) {
        mx[h] = -INFINITY; sm[h] = 0.f;
        s2v[h] = s2[((size_t)(b * NH + h)) * M + m];
    }
    for (int n = threadIdx.x; n < N; n += 256) {
        int a = adjT ? adj[((size_t)(b * M + m)) * N + n]
                     : adj[((size_t)(b * N + n)) * M + m];
#pragma unroll
        for (int h = 0; h < NH; h++) {
            float e;
            if (a > 0) { float x = s1[((size_t)(b * NH + h)) * N + n] + s2v[h];
                         e = x > 0.f ? x : ALPHAF * x; }
            else e = NEGV;
            if (e > mx[h]) { sm[h] = sm[h] * expf(mx[h] - e) + 1.f; mx[h] = e; }
            else sm[h] += expf(e - mx[h]);
        }
    }
    __shared__ float shm[256], shs[256];
    for (int h = 0; h < NH; h++) {
        shm[threadIdx.x] = mx[h]; shs[threadIdx.x] = sm[h];
        __syncthreads();
        for (int st = 128; st > 0; st >>= 1) {
            if (threadIdx.x < st) {
                float m1 = shm[threadIdx.x], s1x = shs[threadIdx.x];
                float m2 = shm[threadIdx.x + st], s2x = shs[threadIdx.x + st];
                float Mx = fmaxf(m1, m2);
                float S = (Mx == -INFINITY) ? 0.f
                        : s1x * expf(m1 - Mx) + s2x * expf(m2 - Mx);
                shm[threadIdx.x] = Mx; shs[threadIdx.x] = S;
            }
            __syncthreads();
        }
        if (threadIdx.x == 0) {
            cmax[((size_t)(b * NH + h)) * M + m] = shm[0];
            csum[((size_t)(b * NH + h)) * M + m] = shs[0];
        }
        __syncthreads();
    }
}

// ---------------- AV: out[b,n,h*64+d] = elu( sum_m p(n,m) * Pk[b,m,h*64+d] ) ----------------
__global__ __launch_bounds__(256) void attn_av(const int* __restrict__ adj, int adjT,
                                               const float* __restrict__ s1,
                                               const float* __restrict__ s2,
                                               const float* __restrict__ cmax,
                                               const float* __restrict__ csum,
                                               const float* __restrict__ Pk,
                                               float* __restrict__ out, int N, int M) {
    const int bh = blockIdx.z;
    const int b = bh >> 3, h = bh & 7;
    const int n0 = blockIdx.y * 64;
    __shared__ float Ps[16][64];   // [m][n] softmax weights
    __shared__ float Ks[16][64];   // [m][d]
    const int tid = threadIdx.x;
    const int tx = tid & 15, ty = tid >> 4;
    const int mm = tid >> 4;
    const int c4 = (tid & 15) << 2;
    const float* s1p = s1 + (size_t)bh * N;
    const float* s2p = s2 + (size_t)bh * M;
    const float* cmp = cmax + (size_t)bh * M;
    const float* csp = csum + (size_t)bh * M;
    float acc[4][4] = {};
    for (int m0 = 0; m0 < M; m0 += 16) {
        int m = m0 + mm;
        float s2v = s2p[m], cm = cmp[m], ics = 1.f / csp[m];
#pragma unroll
        for (int j = 0; j < 4; j++) {
            int n = n0 + c4 + j;
            int a = adjT ? adj[((size_t)(b * M + m)) * N + n]
                         : adj[((size_t)(b * N + n)) * M + m];
            float e;
            if (a > 0) { float x = s1p[n] + s2v; e = x > 0.f ? x : ALPHAF * x; }
            else e = NEGV;
            Ps[mm][c4 + j] = expf(e - cm) * ics;
        }
        float4 kv = *(const float4*)(Pk + ((size_t)(b * M + m)) * NF + h * HD + c4);
        Ks[mm][c4 + 0] = kv.x; Ks[mm][c4 + 1] = kv.y;
        Ks[mm][c4 + 2] = kv.z; Ks[mm][c4 + 3] = kv.w;
        __syncthreads();
#pragma unroll
        for (int k = 0; k < 16; k++) {
            float a_[4], b_[4];
#pragma unroll
            for (int i = 0; i < 4; i++) a_[i] = Ps[k][(ty << 2) + i];
#pragma unroll
            for (int j = 0; j < 4; j++) b_[j] = Ks[k][(tx << 2) + j];
#pragma unroll
            for (int i = 0; i < 4; i++)
#pragma unroll
                for (int j = 0; j < 4; j++) acc[i][j] += a_[i] * b_[j];
        }
        __syncthreads();
    }
#pragma unroll
    for (int i = 0; i < 4; i++) {
        int n = n0 + (ty << 2) + i;
#pragma unroll
        for (int j = 0; j < 4; j++) {
            int d = (tx << 2) + j;
            float v = acc[i][j];
            v = v > 0.f ? v : expm1f(v);
            out[((size_t)(b * N + n)) * NF + h * HD + d] = v;
        }
    }
}

// ---------------- fusion elementwise: out = sig(T2)*T1 + (1-sig)*a ----------------
__global__ void fuse_ew(const float* __restrict__ a, const float* __restrict__ T1,
                        const float* __restrict__ T2, float* __restrict__ out, int n) {
    int i = blockIdx.x * blockDim.x + threadIdx.x;
    if (i < n) {
        float f = 1.f / (1.f + expf(-T2[i]));
        out[i] = f * T1[i] + (1.f - f) * a[i];
    }
}

// ===================== host orchestration =====================
struct Scratch {
    float *Ga, *Ca, *Qa, *G1, *AGG, *Pq, *Pk, *T1, *T2, *Wt;
    float *s1, *s2, *cmax, *csum;
};

static void run_fusion(const float* a, const float* bb,
                       const float* W, const float* U,
                       const float* Wf, const float* Uf,
                       Scratch& S, float* out, int M) {
    dim3 g(NF / 64, M / 64);
    gemm_nn<0><<<g, 256>>>(a,  W,  S.T1, M, NF, NF);
    gemm_nn<1><<<g, 256>>>(bb, U,  S.T1, M, NF, NF);
    gemm_nn<0><<<g, 256>>>(a,  Wf, S.T2, M, NF, NF);
    gemm_nn<1><<<g, 256>>>(bb, Uf, S.T2, M, NF, NF);
    int n = M * NF;
    fuse_ew<<<(n + 255) / 256, 256>>>(a, S.T1, S.T2, out, n);
}

static void run_attn(const float* q, const float* kv, const int* adj, int adjT,
                     int N, int M, const float* W, const float* a1, const float* a2,
                     float* out, Scratch& S) {
    transposeW<<<(NF * NF + 255) / 256, 256>>>(W, S.Wt);
    gemm_nn<0><<<dim3(NF / 64, BATCH * N / 64), 256>>>(q,  S.Wt, S.Pq, BATCH * N, NF, NF);
    gemm_nn<0><<<dim3(NF / 64, BATCH * M / 64), 256>>>(kv, S.Wt, S.Pk, BATCH * M, NF, NF);
    scores_k<<<(BATCH * NH * N + 255) / 256, 256>>>(S.Pq, a1, S.s1, N);
    scores_k<<<(BATCH * NH * M + 255) / 256, 256>>>(S.Pk, a2, S.s2, M);
    colstats_k<<<dim3(M, BATCH), 256>>>(adj, adjT, S.s1, S.s2, S.cmax, S.csum, N, M);
    attn_av<<<dim3(1, N / 64, BATCH * NH), 256>>>(adj, adjT, S.s1, S.s2,
                                                  S.cmax, S.csum, S.Pk, out, N, M);
}

static void run_layer(int l,
                      const float* G, const float* C, const float* Q,
                      float* Gout, float* Cout, float* Qout,
                      const int* g2c, const int* g2q,
                      const float* c2gW, const float* c2ga1, const float* c2ga2,
                      const float* g2qW, const float* g2qa1, const float* g2qa2,
                      const float* q2gW, const float* q2ga1, const float* q2ga2,
                      const float* fusW, const float* fusU,
                      const float* fusWf, const float* fusUf,
                      Scratch& S) {
    const size_t FW = (size_t)NF * NF;
    const size_t AW = (size_t)NH * NF * HD;
    const size_t AV = (size_t)NH * HD;
#define FUS(idx) fusW + (size_t)(l*4+(idx))*FW, fusU + (size_t)(l*4+(idx))*FW, \
                 fusWf + (size_t)(l*4+(idx))*FW, fusUf + (size_t)(l*4+(idx))*FW

    // 1. gloss_same = adj^T @ gloss
    gemm_adjT<<<dim3(NF / 64, NC / 64, BATCH), 256>>>(g2c, G, S.AGG, NG, NC, NF);
    // 2. clip_new = fusion(clip, gloss_same)           [fus idx 0]
    run_fusion(C, S.AGG, FUS(0), S, Cout, BATCH * NC);
    // 3. clip_agg = attn(gloss, clip, g2c)             [c2g]
    run_attn(G, C, g2c, 0, NG, NC, c2gW + l * AW, c2ga1 + l * AV, c2ga2 + l * AV, S.AGG, S);
    // 4. gloss_1 = fusion(gloss, clip_agg)             [fus idx 1]
    run_fusion(G, S.AGG, FUS(1), S, S.G1, BATCH * NG);
    // 5. gloss_agg = attn(question, gloss, g2q^T)      [g2q]
    run_attn(Q, G, g2q, 1, NQ, NG, g2qW + l * AW, g2qa1 + l * AV, g2qa2 + l * AV, S.AGG, S);
    // 6. question_new = fusion(question, gloss_agg)    [fus idx 2]
    run_fusion(Q, S.AGG, FUS(2), S, Qout, BATCH * NQ);
    // 7. question_agg = attn(gloss, question, g2q)     [q2g]
    run_attn(G, Q, g2q, 0, NG, NQ, q2gW + l * AW, q2ga1 + l * AV, q2ga2 + l * AV, S.AGG, S);
    // 8. gloss_new = fusion(gloss_1, question_agg)     [fus idx 3]
    run_fusion(S.G1, S.AGG, FUS(3), S, Gout, BATCH * NG);
#undef FUS
}

static float* symaddr(const void* sym) {
    void* p = nullptr;
    cudaGetSymbolAddress(&p, sym);
    return (float*)p;
}

extern "C" void kernel_launch(void* const* d_in, const int* in_sizes, int n_in,
                              void* d_out, int out_size) {
    (void)in_sizes; (void)n_in; (void)out_size;
    Scratch S;
    S.Ga = symaddr(g_Ga);   S.Ca = symaddr(g_Ca);   S.Qa = symaddr(g_Qa);
    S.G1 = symaddr(g_G1);   S.AGG = symaddr(g_AGG);
    S.Pq = symaddr(g_Pq);   S.Pk = symaddr(g_Pk);
    S.T1 = symaddr(g_T1);   S.T2 = symaddr(g_T2);   S.Wt = symaddr(g_Wt);
    S.s1 = symaddr(g_s1);   S.s2 = symaddr(g_s2);
    S.cmax = symaddr(g_cmax); S.csum = symaddr(g_csum);

    const float* gloss    = (const float*)d_in[0];
    const float* clip     = (const float*)d_in[1];
    const float* question = (const float*)d_in[2];
    const int*   g2c      = (const int*)d_in[3];
    const int*   g2q      = (const int*)d_in[4];
    const float* c2gW  = (const float*)d_in[5];
    const float* c2ga1 = (const float*)d_in[6];
    const float* c2ga2 = (const float*)d_in[7];
    const float* g2qW  = (const float*)d_in[8];
    const float* g2qa1 = (const float*)d_in[9];
    const float* g2qa2 = (const float*)d_in[10];
    const float* q2gW  = (const float*)d_in[11];
    const float* q2ga1 = (const float*)d_in[12];
    const float* q2ga2 = (const float*)d_in[13];
    const float* fusW  = (const float*)d_in[14];
    const float* fusU  = (const float*)d_in[15];
    const float* fusWf = (const float*)d_in[16];
    const float* fusUf = (const float*)d_in[17];

    float* out = (float*)d_out;
    float* outG = out;                                   // gloss  [B,NG,NF]
    float* outC = out + (size_t)BATCH * NG * NF;         // clip   [B,NC,NF]
    float* outQ = outC + (size_t)BATCH * NC * NF;        // question [B,NQ,NF]

    // Layer 0: inputs -> scratch
    run_layer(0, gloss, clip, question, S.Ga, S.Ca, S.Qa,
              g2c, g2q, c2gW, c2ga1, c2ga2, g2qW, g2qa1, g2qa2,
              q2gW, q2ga1, q2ga2, fusW, fusU, fusWf, fusUf, S);
    // Layer 1: scratch -> d_out (fusion kernels write final buffers directly)
    run_layer(1, S.Ga, S.Ca, S.Qa, outG, outC, outQ,
              g2c, g2q, c2gW, c2ga1, c2ga2, g2qW, g2qa1, g2qa2,
              q2gW, q2ga1, q2ga2, fusW, fusU, fusWf, fusUf, S);
}